// round 5
// baseline (speedup 1.0000x reference)
#include <cuda_runtime.h>
#include <cuda_bf16.h>
#include <cstdint>

// TSM: x (B=4, T=16, H=64, W=64, C=256) fp32
// out[..., 0:64)    = x[t+1, ..., 0:64)   (0 at t=T-1)
// out[..., 64:128)  = x[t-1, ..., 64:128) (0 at t=0)
// out[..., 128:256) = x[t, ..., 128:256)
//
// R5: warp-uniform dt mapping.
// float4 units: 64 per pixel. Channel groups of 16 f4: g0 dt=+1, g1 dt=-1, g2,g3 dt=0.
// Block = 1024 f4 = 16 pixels (TPB 256 x U4), aligned inside a (b,t) slab
// (slab = 1<<18 f4 = 256 blocks), so t is uniform per block.
// Warp-tile (w,u) = pixels {2w, 2w+1} x group u:
//   lane l -> pixel 2w + (l>>4), c4 = u*16 + (l&15)
// -> each LDG/STG touches ONE slab (two 256B chunks 1KB apart), dt is a
//    compile-time constant per u, and boundary zeroing is a uniform branch.

static constexpr int BTSTRIDE = 1 << 18;      // float4 per (b,t) slab
static constexpr long long N4 = 16777216LL;   // total float4
static constexpr int TPB = 256;
static constexpr int F4_PER_BLOCK = 1024;

__global__ __launch_bounds__(TPB) void tsm_kernel(const float4* __restrict__ in,
                                                  float4* __restrict__ out)
{
    const int bid = blockIdx.x;
    const long long blockBase = (long long)bid * F4_PER_BLOCK;
    const int t = (bid >> 8) & 15;              // 256 blocks per slab

    const int tid  = threadIdx.x;
    const int w    = tid >> 5;
    const int l    = tid & 31;
    // base offset within block for this lane (pixel-pair + lane-within-group)
    const int off  = ((w << 1) + (l >> 4)) * 64 + (l & 15);
    const long long i0 = blockBase + off;       // u=0 index; i_u = i0 + u*16

    float4 v0 = make_float4(0.f, 0.f, 0.f, 0.f);
    float4 v1 = make_float4(0.f, 0.f, 0.f, 0.f);
    float4 v2, v3;

    // u=0: dt=+1, valid if t < 15  (uniform branch)
    if (t < 15) v0 = __ldcs(&in[i0 + BTSTRIDE]);
    // u=1: dt=-1, valid if t > 0
    if (t > 0)  v1 = __ldcs(&in[i0 + 16 - BTSTRIDE]);
    // u=2,3: identity
    v2 = __ldcs(&in[i0 + 32]);
    v3 = __ldcs(&in[i0 + 48]);

    __stcs(&out[i0],      v0);
    __stcs(&out[i0 + 16], v1);
    __stcs(&out[i0 + 32], v2);
    __stcs(&out[i0 + 48], v3);
}

extern "C" void kernel_launch(void* const* d_in, const int* in_sizes, int n_in,
                              void* d_out, int out_size)
{
    const float4* in = (const float4*)d_in[0];
    float4* out = (float4*)d_out;

    int blocks = (int)(N4 / F4_PER_BLOCK); // 16384
    tsm_kernel<<<blocks, TPB>>>(in, out);
}